// round 5
// baseline (speedup 1.0000x reference)
#include <cuda_runtime.h>
#include <cuda_bf16.h>
#include <math.h>

#define NN 100000
#define NE 1600000
#define SCAN_BS 512
#define NBLK ((NN + SCAN_BS - 1) / SCAN_BS)   // 196

// -------- packed f32x2 helpers (Blackwell FFMA2 path, PTX-only) ------------
__device__ __forceinline__ void ffma2(unsigned long long& d,
                                      unsigned long long a,
                                      unsigned long long b,
                                      unsigned long long c) {
    asm("fma.rn.f32x2 %0, %1, %2, %3;" : "=l"(d) : "l"(a), "l"(b), "l"(c));
}
__device__ __forceinline__ unsigned long long pack2(float lo, float hi) {
    unsigned long long r;
    asm("mov.b64 %0, {%1, %2};" : "=l"(r) : "f"(lo), "f"(hi));
    return r;
}
__device__ __forceinline__ void unpack2(float& lo, float& hi, unsigned long long v) {
    asm("mov.b64 {%0, %1}, %2;" : "=f"(lo), "=f"(hi) : "l"(v));
}

// -------- device scratch (allocation-free rule: __device__ globals) --------
__device__ float g_deginv[NN];
__device__ int   g_degi[NN];
__device__ int   g_cursor[NN];
__device__ int   g_rowptr[NN + 1];
__device__ int   g_rowtmp[NN];
__device__ int   g_blocksum[NBLK];
__device__ int   g_blockoff[NBLK];
__device__ int   g_col[NE];                  // CSR: src ids grouped by dst
__device__ float g_bufA[NN * 64];            // yl = h @ Wl
__device__ float g_bufB[NN * 64];            // yr = h @ Wr + b
__device__ float g_h[NN * 64];               // layer activations

// ---------------------------------------------------------------------------
// CSR build (edge structure fixed across layers -> once per call)
// ---------------------------------------------------------------------------
__global__ void zero_int_kernel() {
    int i = blockIdx.x * blockDim.x + threadIdx.x;
    if (i < NN) { g_degi[i] = 0; g_cursor[i] = 0; }
}

__global__ void deg_count_kernel(const int* __restrict__ dst) {
    int e = blockIdx.x * blockDim.x + threadIdx.x;
    if (e < NE) atomicAdd(&g_degi[dst[e]], 1);
}

__global__ void scan_a_kernel() {
    __shared__ int s[SCAN_BS];
    int t = threadIdx.x;
    int i = blockIdx.x * SCAN_BS + t;
    int v = (i < NN) ? g_degi[i] : 0;
    s[t] = v;
    __syncthreads();
#pragma unroll
    for (int off = 1; off < SCAN_BS; off <<= 1) {
        int x = (t >= off) ? s[t - off] : 0;
        __syncthreads();
        s[t] += x;
        __syncthreads();
    }
    if (i < NN) g_rowtmp[i] = s[t] - v;           // exclusive
    if (t == SCAN_BS - 1) g_blocksum[blockIdx.x] = s[t];
}

__global__ void scan_b_kernel() {
    __shared__ int s[256];
    int t = threadIdx.x;
    int v = (t < NBLK) ? g_blocksum[t] : 0;
    s[t] = v;
    __syncthreads();
#pragma unroll
    for (int off = 1; off < 256; off <<= 1) {
        int x = (t >= off) ? s[t - off] : 0;
        __syncthreads();
        s[t] += x;
        __syncthreads();
    }
    if (t < NBLK) g_blockoff[t] = s[t] - v;       // exclusive
}

__global__ void scan_c_kernel() {
    int i = blockIdx.x * blockDim.x + threadIdx.x;
    if (i < NN) {
        g_rowptr[i] = g_rowtmp[i] + g_blockoff[i / SCAN_BS];
        g_deginv[i] = 1.0f / fmaxf((float)g_degi[i], 1.0f);
    }
    if (i == 0) g_rowptr[NN] = NE;
}

__global__ void csr_fill_kernel(const int* __restrict__ src,
                                const int* __restrict__ dst) {
    int e = blockIdx.x * blockDim.x + threadIdx.x;
    if (e >= NE) return;
    int d = dst[e];
    int pos = g_rowptr[d] + atomicAdd(&g_cursor[d], 1);
    g_col[pos] = src[e];
}

// ---------------------------------------------------------------------------
// Dual projection: yl = h @ Wl ; yr = h @ Wr + b.  DIN fixed at 64.
// 4 nodes x 4 j per thread; (Wl,Wr) accumulators PAIRED in 64-bit regs and
// advanced with fma.rn.f32x2 (FFMA2): 16 packed FMAs per k-step instead of
// 32 scalar. Weights staged interleaved in shared: sW2[k][j] = (wl, wr).
//   DOUT=64: JG=16, NPB=64,  smem = 16K(h) + 32K(w-pairs) = 48K
//   DOUT=32: JG=8,  NPB=128, smem = 32K(h) + 16K(w-pairs) = 48K
template<int DOUT, bool FROM_GH>
__global__ void __launch_bounds__(256, 4)
gemm_dual_kernel(const float* __restrict__ hx,
                 const float* __restrict__ Wl,
                 const float* __restrict__ Wr,
                 const float* __restrict__ bias) {
    constexpr int JG  = DOUT / 4;
    constexpr int NPB = 256 / JG * 4;
    constexpr int KC  = 64 * NPB / 256;

    __shared__ alignas(16) float sh[64][NPB];          // k-major h tile
    __shared__ alignas(16) float sW2[64 * DOUT * 2];   // interleaved (wl,wr)

    const float* __restrict__ h = FROM_GH ? (const float*)g_h : hx;

    const int t     = threadIdx.x;
    const int node0 = blockIdx.x * NPB;

    // ---- stage h tile, transposing to k-major ----
    {
        const int r  = t % NPB;
        const int c0 = (t / NPB) * KC;
        const int n  = node0 + r;
        const bool ok = (n < NN);
#pragma unroll
        for (int i = 0; i < KC; i += 4) {
            float4 v = ok ? *(const float4*)&h[(size_t)n * 64 + c0 + i]
                          : make_float4(0.f, 0.f, 0.f, 0.f);
            sh[c0 + i + 0][r] = v.x;
            sh[c0 + i + 1][r] = v.y;
            sh[c0 + i + 2][r] = v.z;
            sh[c0 + i + 3][r] = v.w;
        }
    }
    // ---- stage interleaved weight pairs ----
    for (int i = t; i < 64 * DOUT; i += 256) {
        sW2[2 * i + 0] = Wl[i];
        sW2[2 * i + 1] = Wr[i];
    }
    __syncthreads();

    const int jg = t % JG;          // j-group (4 outputs)
    const int ng = t / JG;          // node-group (4 nodes)

    // acc[n][j] = packed (aL, aR)
    unsigned long long acc[4][4];
    {
        float b0 = bias[jg * 4 + 0];
        float b1 = bias[jg * 4 + 1];
        float b2 = bias[jg * 4 + 2];
        float b3 = bias[jg * 4 + 3];
#pragma unroll
        for (int n = 0; n < 4; n++) {
            acc[n][0] = pack2(0.f, b0);
            acc[n][1] = pack2(0.f, b1);
            acc[n][2] = pack2(0.f, b2);
            acc[n][3] = pack2(0.f, b3);
        }
    }

#pragma unroll 8
    for (int k = 0; k < 64; k++) {
        const float4 hv = *(const float4*)&sh[k][ng * 4];
        // two LDS.128 -> 4 (wl,wr) pairs for j = jg*4 .. jg*4+3
        const ulonglong2 wp01 = *(const ulonglong2*)&sW2[(k * DOUT + jg * 4) * 2];
        const ulonglong2 wp23 = *(const ulonglong2*)&sW2[(k * DOUT + jg * 4) * 2 + 4];
        const unsigned long long w[4] = {wp01.x, wp01.y, wp23.x, wp23.y};
        const unsigned long long hp[4] = {
            pack2(hv.x, hv.x), pack2(hv.y, hv.y),
            pack2(hv.z, hv.z), pack2(hv.w, hv.w)};
#pragma unroll
        for (int n = 0; n < 4; n++) {
#pragma unroll
            for (int j = 0; j < 4; j++) {
                ffma2(acc[n][j], hp[n], w[j], acc[n][j]);
            }
        }
    }

    // ---- epilogue: unpack, float4 stores ----
#pragma unroll
    for (int n = 0; n < 4; n++) {
        const int node = node0 + ng * 4 + n;
        if (node < NN) {
            float l0, r0, l1, r1, l2, r2, l3, r3;
            unpack2(l0, r0, acc[n][0]);
            unpack2(l1, r1, acc[n][1]);
            unpack2(l2, r2, acc[n][2]);
            unpack2(l3, r3, acc[n][3]);
            *(float4*)&g_bufA[(size_t)node * DOUT + jg * 4] =
                make_float4(l0, l1, l2, l3);
            *(float4*)&g_bufB[(size_t)node * DOUT + jg * 4] =
                make_float4(r0, r1, r2, r3);
        }
    }
}

// ---------------------------------------------------------------------------
// Fused gather + epilogue: out[n] = [ELU]( mean_{e in row(n)} yl[col[e]] + yr[n] )
template<int F, bool DO_ELU, bool TO_GH>
__global__ void __launch_bounds__(256)
gather_kernel(float* __restrict__ out_param) {
    constexpr int L = F / 4;               // 16 (F=64) or 8 (F=32)
    const int t    = threadIdx.x;
    const int grp  = t / L;
    const int lane = t % L;
    const int node = blockIdx.x * (256 / L) + grp;
    if (node >= NN) return;

    const int beg = g_rowptr[node];
    const int end = g_rowptr[node + 1];
    const float4* __restrict__ A = (const float4*)g_bufA;

    float4 a0 = make_float4(0.f, 0.f, 0.f, 0.f);
    float4 a1 = make_float4(0.f, 0.f, 0.f, 0.f);
    int e = beg;
    for (; e + 2 <= end; e += 2) {
        int s0 = g_col[e];
        int s1 = g_col[e + 1];
        float4 v0 = A[(size_t)s0 * L + lane];
        float4 v1 = A[(size_t)s1 * L + lane];
        a0.x += v0.x; a0.y += v0.y; a0.z += v0.z; a0.w += v0.w;
        a1.x += v1.x; a1.y += v1.y; a1.z += v1.z; a1.w += v1.w;
    }
    if (e < end) {
        int s0 = g_col[e];
        float4 v0 = A[(size_t)s0 * L + lane];
        a0.x += v0.x; a0.y += v0.y; a0.z += v0.z; a0.w += v0.w;
    }

    const float di = g_deginv[node];
    const float4 r = ((const float4*)g_bufB)[(size_t)node * L + lane];
    float4 o;
    o.x = fmaf(a0.x + a1.x, di, r.x);
    o.y = fmaf(a0.y + a1.y, di, r.y);
    o.z = fmaf(a0.z + a1.z, di, r.z);
    o.w = fmaf(a0.w + a1.w, di, r.w);
    if (DO_ELU) {
        o.x = (o.x > 0.f) ? o.x : expm1f(o.x);
        o.y = (o.y > 0.f) ? o.y : expm1f(o.y);
        o.z = (o.z > 0.f) ? o.z : expm1f(o.z);
        o.w = (o.w > 0.f) ? o.w : expm1f(o.w);
    }
    float* out = TO_GH ? (float*)g_h : out_param;
    ((float4*)out)[(size_t)node * L + lane] = o;
}

// ---------------------------------------------------------------------------
extern "C" void kernel_launch(void* const* d_in, const int* in_sizes, int n_in,
                              void* d_out, int out_size) {
    const float* x   = (const float*)d_in[0];
    const int*   ei  = (const int*)d_in[1];
    const float* Wl0 = (const float*)d_in[2];
    const float* Wr0 = (const float*)d_in[3];
    const float* b0  = (const float*)d_in[4];
    const float* Wl1 = (const float*)d_in[5];
    const float* Wr1 = (const float*)d_in[6];
    const float* b1  = (const float*)d_in[7];
    const float* Wl2 = (const float*)d_in[8];
    const float* Wr2 = (const float*)d_in[9];
    const float* b2  = (const float*)d_in[10];
    float* out = (float*)d_out;

    const int* src = ei;
    const int* dst = ei + NE;

    const int TPB = 256;
    const int gemm_blocks64 = (NN + 63) / 64;
    const int gemm_blocks32 = (NN + 127) / 128;
    const int gather_blocks64 = (NN + 15) / 16;
    const int gather_blocks32 = (NN + 31) / 32;

    // ---- CSR build (once; structure shared by all layers) ----
    zero_int_kernel<<<(NN + TPB - 1) / TPB, TPB>>>();
    deg_count_kernel<<<(NE + TPB - 1) / TPB, TPB>>>(dst);
    scan_a_kernel<<<NBLK, SCAN_BS>>>();
    scan_b_kernel<<<1, 256>>>();
    scan_c_kernel<<<(NN + TPB - 1) / TPB, TPB>>>();
    csr_fill_kernel<<<(NE + TPB - 1) / TPB, TPB>>>(src, dst);

    // ---- layer 0: 64 -> 64, ELU ----
    gemm_dual_kernel<64, false><<<gemm_blocks64, 256>>>(x, Wl0, Wr0, b0);
    gather_kernel<64, true, true><<<gather_blocks64, 256>>>(nullptr);

    // ---- layer 1: 64 -> 64, ELU ----
    gemm_dual_kernel<64, true><<<gemm_blocks64, 256>>>(nullptr, Wl1, Wr1, b1);
    gather_kernel<64, true, true><<<gather_blocks64, 256>>>(nullptr);

    // ---- layer 2: 64 -> 32, no activation, straight to d_out ----
    gemm_dual_kernel<32, true><<<gemm_blocks32, 256>>>(nullptr, Wl2, Wr2, b2);
    gather_kernel<32, false, false><<<gather_blocks32, 256>>>(out);
}

// round 6
// speedup vs baseline: 1.2255x; 1.2255x over previous
#include <cuda_runtime.h>
#include <cuda_bf16.h>
#include <math.h>

#define NN 100000
#define NE 1600000
#define SCAN_BS 512
#define NBLK ((NN + SCAN_BS - 1) / SCAN_BS)   // 196

// -------- device scratch (allocation-free rule: __device__ globals) --------
__device__ float g_deginv[NN];
__device__ int   g_degi[NN];
__device__ int   g_cursor[NN];
__device__ int   g_rowptr[NN + 1];
__device__ int   g_rowtmp[NN];
__device__ int   g_blocksum[NBLK];
__device__ int   g_blockoff[NBLK];
__device__ int   g_col[NE];                  // CSR: src ids grouped by dst
__device__ float g_bufA[NN * 64];            // yl = h @ Wl
__device__ float g_bufB[NN * 64];            // yr = h @ Wr + b
__device__ float g_h[NN * 64];               // layer activations

// ---------------------------------------------------------------------------
// CSR build (edge structure fixed across layers -> once per call)
// ---------------------------------------------------------------------------
__global__ void zero_int_kernel() {
    int i = blockIdx.x * blockDim.x + threadIdx.x;
    if (i < NN) { g_degi[i] = 0; g_cursor[i] = 0; }
}

__global__ void deg_count_kernel(const int* __restrict__ dst) {
    int e = blockIdx.x * blockDim.x + threadIdx.x;
    if (e < NE) atomicAdd(&g_degi[dst[e]], 1);
}

__global__ void scan_a_kernel() {
    __shared__ int s[SCAN_BS];
    int t = threadIdx.x;
    int i = blockIdx.x * SCAN_BS + t;
    int v = (i < NN) ? g_degi[i] : 0;
    s[t] = v;
    __syncthreads();
#pragma unroll
    for (int off = 1; off < SCAN_BS; off <<= 1) {
        int x = (t >= off) ? s[t - off] : 0;
        __syncthreads();
        s[t] += x;
        __syncthreads();
    }
    if (i < NN) g_rowtmp[i] = s[t] - v;           // exclusive
    if (t == SCAN_BS - 1) g_blocksum[blockIdx.x] = s[t];
}

__global__ void scan_b_kernel() {
    __shared__ int s[256];
    int t = threadIdx.x;
    int v = (t < NBLK) ? g_blocksum[t] : 0;
    s[t] = v;
    __syncthreads();
#pragma unroll
    for (int off = 1; off < 256; off <<= 1) {
        int x = (t >= off) ? s[t - off] : 0;
        __syncthreads();
        s[t] += x;
        __syncthreads();
    }
    if (t < NBLK) g_blockoff[t] = s[t] - v;       // exclusive
}

__global__ void scan_c_kernel() {
    int i = blockIdx.x * blockDim.x + threadIdx.x;
    if (i < NN) {
        g_rowptr[i] = g_rowtmp[i] + g_blockoff[i / SCAN_BS];
        g_deginv[i] = 1.0f / fmaxf((float)g_degi[i], 1.0f);
    }
    if (i == 0) g_rowptr[NN] = NE;
}

__global__ void csr_fill_kernel(const int* __restrict__ src,
                                const int* __restrict__ dst) {
    int e = blockIdx.x * blockDim.x + threadIdx.x;
    if (e >= NE) return;
    int d = dst[e];
    int pos = g_rowptr[d] + atomicAdd(&g_cursor[d], 1);
    g_col[pos] = src[e];
}

// ---------------------------------------------------------------------------
// Dual projection: yl = h @ Wl ; yr = h @ Wr + b.  DIN fixed at 64.
// SCALAR FFMA (round-4 form; packed-f32x2 variant regressed).
// Register tile: 8 nodes x 4 j per thread (64 FFMA per k-step, 4 LDS.128)
// -> better FFMA:LDS ratio than the 4x4 tile. k staged in two phases of 32
// so static smem stays small:
//   DOUT=64: JG=16, NPB=128 nodes/block, smem = 16K(h) + 2*8K(w) = 32K
//   DOUT=32: JG=8,  NPB=256 nodes/block, smem = 32K(h) + 2*4K(w) = 40K
template<int DOUT, bool FROM_GH>
__global__ void __launch_bounds__(256, 2)
gemm_dual_kernel(const float* __restrict__ hx,
                 const float* __restrict__ Wl,
                 const float* __restrict__ Wr,
                 const float* __restrict__ bias) {
    constexpr int JG  = DOUT / 4;          // j-groups of width 4
    constexpr int NG  = 256 / JG;          // node-groups per block
    constexpr int NPB = NG * 8;            // nodes per block (128 or 256)
    constexpr int KC  = 32 * NPB / 256;    // k's staged per thread per phase

    __shared__ alignas(16) float sh[32][NPB];     // k-major h half-tile
    __shared__ alignas(16) float sWl[32 * DOUT];
    __shared__ alignas(16) float sWr[32 * DOUT];

    const float* __restrict__ h = FROM_GH ? (const float*)g_h : hx;

    const int t     = threadIdx.x;
    const int node0 = blockIdx.x * NPB;
    const int jg    = t % JG;              // j-group (4 outputs)
    const int ng    = t / JG;              // node-group (8 nodes)

    float aL[8][4], aR[8][4];
#pragma unroll
    for (int n = 0; n < 8; n++)
#pragma unroll
        for (int j = 0; j < 4; j++) {
            aL[n][j] = 0.f;
            aR[n][j] = bias[jg * 4 + j];
        }

#pragma unroll
    for (int phase = 0; phase < 2; phase++) {
        const int kbase = phase * 32;
        if (phase) __syncthreads();        // protect smem reuse

        // ---- stage h half-tile, transposing to k-major ----
        {
            const int r  = t % NPB;
            const int c0 = (t / NPB) * KC;
            const int n  = node0 + r;
            const bool ok = (n < NN);
#pragma unroll
            for (int i = 0; i < KC; i += 4) {
                float4 v = ok ? *(const float4*)&h[(size_t)n * 64 + kbase + c0 + i]
                              : make_float4(0.f, 0.f, 0.f, 0.f);
                sh[c0 + i + 0][r] = v.x;
                sh[c0 + i + 1][r] = v.y;
                sh[c0 + i + 2][r] = v.z;
                sh[c0 + i + 3][r] = v.w;
            }
        }
        // ---- stage weight half-tiles (rows kbase..kbase+31) ----
        for (int i = t; i < 32 * DOUT; i += 256) {
            sWl[i] = Wl[kbase * DOUT + i];
            sWr[i] = Wr[kbase * DOUT + i];
        }
        __syncthreads();

#pragma unroll 8
        for (int k = 0; k < 32; k++) {
            const float4 hv0 = *(const float4*)&sh[k][ng * 8];
            const float4 hv1 = *(const float4*)&sh[k][ng * 8 + 4];
            const float4 wl  = *(const float4*)&sWl[k * DOUT + jg * 4];
            const float4 wr  = *(const float4*)&sWr[k * DOUT + jg * 4];
            const float hn[8]  = {hv0.x, hv0.y, hv0.z, hv0.w,
                                  hv1.x, hv1.y, hv1.z, hv1.w};
            const float wlj[4] = {wl.x, wl.y, wl.z, wl.w};
            const float wrj[4] = {wr.x, wr.y, wr.z, wr.w};
#pragma unroll
            for (int n = 0; n < 8; n++) {
#pragma unroll
                for (int j = 0; j < 4; j++) {
                    aL[n][j] = fmaf(hn[n], wlj[j], aL[n][j]);
                    aR[n][j] = fmaf(hn[n], wrj[j], aR[n][j]);
                }
            }
        }
    }

    // ---- epilogue: float4 stores, coalesced across jg ----
#pragma unroll
    for (int n = 0; n < 8; n++) {
        const int node = node0 + ng * 8 + n;
        if (node < NN) {
            *(float4*)&g_bufA[(size_t)node * DOUT + jg * 4] =
                make_float4(aL[n][0], aL[n][1], aL[n][2], aL[n][3]);
            *(float4*)&g_bufB[(size_t)node * DOUT + jg * 4] =
                make_float4(aR[n][0], aR[n][1], aR[n][2], aR[n][3]);
        }
    }
}

// ---------------------------------------------------------------------------
// Fused gather + epilogue: out[n] = [ELU]( mean_{e in row(n)} yl[col[e]] + yr[n] )
template<int F, bool DO_ELU, bool TO_GH>
__global__ void __launch_bounds__(256)
gather_kernel(float* __restrict__ out_param) {
    constexpr int L = F / 4;               // 16 (F=64) or 8 (F=32)
    const int t    = threadIdx.x;
    const int grp  = t / L;
    const int lane = t % L;
    const int node = blockIdx.x * (256 / L) + grp;
    if (node >= NN) return;

    const int beg = g_rowptr[node];
    const int end = g_rowptr[node + 1];
    const float4* __restrict__ A = (const float4*)g_bufA;

    float4 a0 = make_float4(0.f, 0.f, 0.f, 0.f);
    float4 a1 = make_float4(0.f, 0.f, 0.f, 0.f);
    int e = beg;
    for (; e + 2 <= end; e += 2) {
        int s0 = g_col[e];
        int s1 = g_col[e + 1];
        float4 v0 = A[(size_t)s0 * L + lane];
        float4 v1 = A[(size_t)s1 * L + lane];
        a0.x += v0.x; a0.y += v0.y; a0.z += v0.z; a0.w += v0.w;
        a1.x += v1.x; a1.y += v1.y; a1.z += v1.z; a1.w += v1.w;
    }
    if (e < end) {
        int s0 = g_col[e];
        float4 v0 = A[(size_t)s0 * L + lane];
        a0.x += v0.x; a0.y += v0.y; a0.z += v0.z; a0.w += v0.w;
    }

    const float di = g_deginv[node];
    const float4 r = ((const float4*)g_bufB)[(size_t)node * L + lane];
    float4 o;
    o.x = fmaf(a0.x + a1.x, di, r.x);
    o.y = fmaf(a0.y + a1.y, di, r.y);
    o.z = fmaf(a0.z + a1.z, di, r.z);
    o.w = fmaf(a0.w + a1.w, di, r.w);
    if (DO_ELU) {
        o.x = (o.x > 0.f) ? o.x : expm1f(o.x);
        o.y = (o.y > 0.f) ? o.y : expm1f(o.y);
        o.z = (o.z > 0.f) ? o.z : expm1f(o.z);
        o.w = (o.w > 0.f) ? o.w : expm1f(o.w);
    }
    float* out = TO_GH ? (float*)g_h : out_param;
    ((float4*)out)[(size_t)node * L + lane] = o;
}

// ---------------------------------------------------------------------------
extern "C" void kernel_launch(void* const* d_in, const int* in_sizes, int n_in,
                              void* d_out, int out_size) {
    const float* x   = (const float*)d_in[0];
    const int*   ei  = (const int*)d_in[1];
    const float* Wl0 = (const float*)d_in[2];
    const float* Wr0 = (const float*)d_in[3];
    const float* b0  = (const float*)d_in[4];
    const float* Wl1 = (const float*)d_in[5];
    const float* Wr1 = (const float*)d_in[6];
    const float* b1  = (const float*)d_in[7];
    const float* Wl2 = (const float*)d_in[8];
    const float* Wr2 = (const float*)d_in[9];
    const float* b2  = (const float*)d_in[10];
    float* out = (float*)d_out;

    const int* src = ei;
    const int* dst = ei + NE;

    const int TPB = 256;
    const int gemm_blocks64 = (NN + 127) / 128;   // 782
    const int gemm_blocks32 = (NN + 255) / 256;   // 391
    const int gather_blocks64 = (NN + 15) / 16;
    const int gather_blocks32 = (NN + 31) / 32;

    // ---- CSR build (once; structure shared by all layers) ----
    zero_int_kernel<<<(NN + TPB - 1) / TPB, TPB>>>();
    deg_count_kernel<<<(NE + TPB - 1) / TPB, TPB>>>(dst);
    scan_a_kernel<<<NBLK, SCAN_BS>>>();
    scan_b_kernel<<<1, 256>>>();
    scan_c_kernel<<<(NN + TPB - 1) / TPB, TPB>>>();
    csr_fill_kernel<<<(NE + TPB - 1) / TPB, TPB>>>(src, dst);

    // ---- layer 0: 64 -> 64, ELU ----
    gemm_dual_kernel<64, false><<<gemm_blocks64, 256>>>(x, Wl0, Wr0, b0);
    gather_kernel<64, true, true><<<gather_blocks64, 256>>>(nullptr);

    // ---- layer 1: 64 -> 64, ELU ----
    gemm_dual_kernel<64, true><<<gemm_blocks64, 256>>>(nullptr, Wl1, Wr1, b1);
    gather_kernel<64, true, true><<<gather_blocks64, 256>>>(nullptr);

    // ---- layer 2: 64 -> 32, no activation, straight to d_out ----
    gemm_dual_kernel<32, true><<<gemm_blocks32, 256>>>(nullptr, Wl2, Wr2, b2);
    gather_kernel<32, false, false><<<gather_blocks32, 256>>>(out);
}

// round 7
// speedup vs baseline: 1.2650x; 1.0322x over previous
#include <cuda_runtime.h>
#include <cuda_bf16.h>
#include <math.h>

#define NN 100000
#define NE 1600000
#define SCAN_BS 512
#define NBLK ((NN + SCAN_BS - 1) / SCAN_BS)   // 196

// -------- device scratch (allocation-free rule: __device__ globals) --------
__device__ float g_deginv[NN];
__device__ int   g_degi[NN];
__device__ int   g_cursor[NN];
__device__ int   g_rowptr[NN + 1];
__device__ int   g_rowtmp[NN];
__device__ int   g_blocksum[NBLK];
__device__ int   g_blockoff[NBLK];
__device__ int   g_col[NE];                  // CSR: src ids grouped by dst
__device__ float g_bufA[NN * 64];            // yl = h @ Wl
__device__ float g_bufB[NN * 64];            // yr = h @ Wr + b
__device__ float g_h[NN * 64];               // layer activations

// ---------------------------------------------------------------------------
// CSR build (edge structure fixed across layers -> once per call)
// ---------------------------------------------------------------------------
__global__ void zero_int_kernel() {
    int i = blockIdx.x * blockDim.x + threadIdx.x;
    if (i < NN) { g_degi[i] = 0; g_cursor[i] = 0; }
}

__global__ void deg_count_kernel(const int* __restrict__ dst) {
    int e = blockIdx.x * blockDim.x + threadIdx.x;
    if (e < NE) atomicAdd(&g_degi[dst[e]], 1);
}

__global__ void scan_a_kernel() {
    __shared__ int s[SCAN_BS];
    int t = threadIdx.x;
    int i = blockIdx.x * SCAN_BS + t;
    int v = (i < NN) ? g_degi[i] : 0;
    s[t] = v;
    __syncthreads();
#pragma unroll
    for (int off = 1; off < SCAN_BS; off <<= 1) {
        int x = (t >= off) ? s[t - off] : 0;
        __syncthreads();
        s[t] += x;
        __syncthreads();
    }
    if (i < NN) g_rowtmp[i] = s[t] - v;           // exclusive
    if (t == SCAN_BS - 1) g_blocksum[blockIdx.x] = s[t];
}

__global__ void scan_b_kernel() {
    __shared__ int s[256];
    int t = threadIdx.x;
    int v = (t < NBLK) ? g_blocksum[t] : 0;
    s[t] = v;
    __syncthreads();
#pragma unroll
    for (int off = 1; off < 256; off <<= 1) {
        int x = (t >= off) ? s[t - off] : 0;
        __syncthreads();
        s[t] += x;
        __syncthreads();
    }
    if (t < NBLK) g_blockoff[t] = s[t] - v;       // exclusive
}

__global__ void scan_c_kernel() {
    int i = blockIdx.x * blockDim.x + threadIdx.x;
    if (i < NN) {
        g_rowptr[i] = g_rowtmp[i] + g_blockoff[i / SCAN_BS];
        g_deginv[i] = 1.0f / fmaxf((float)g_degi[i], 1.0f);
    }
    if (i == 0) g_rowptr[NN] = NE;
}

__global__ void csr_fill_kernel(const int* __restrict__ src,
                                const int* __restrict__ dst) {
    int e = blockIdx.x * blockDim.x + threadIdx.x;
    if (e >= NE) return;
    int d = dst[e];
    int pos = g_rowptr[d] + atomicAdd(&g_cursor[d], 1);
    g_col[pos] = src[e];
}

// ---------------------------------------------------------------------------
// Dual projection: yl = h @ Wl ; yr = h @ Wr + b.  DIN fixed at 64.
// SCALAR FFMA; 8 nodes x 4 j per thread (64 FFMA : 4 LDS.128 per k-step),
// k staged in two phases of 32.
//   DOUT=64: JG=16, NPB=128 nodes/block, smem = 16K(h) + 2*8K(w) = 32K
//   DOUT=32: JG=8,  NPB=256 nodes/block, smem = 32K(h) + 2*4K(w) = 40K
template<int DOUT, bool FROM_GH>
__global__ void __launch_bounds__(256, 2)
gemm_dual_kernel(const float* __restrict__ hx,
                 const float* __restrict__ Wl,
                 const float* __restrict__ Wr,
                 const float* __restrict__ bias) {
    constexpr int JG  = DOUT / 4;
    constexpr int NG  = 256 / JG;
    constexpr int NPB = NG * 8;
    constexpr int KC  = 32 * NPB / 256;

    __shared__ alignas(16) float sh[32][NPB];
    __shared__ alignas(16) float sWl[32 * DOUT];
    __shared__ alignas(16) float sWr[32 * DOUT];

    const float* __restrict__ h = FROM_GH ? (const float*)g_h : hx;

    const int t     = threadIdx.x;
    const int node0 = blockIdx.x * NPB;
    const int jg    = t % JG;
    const int ng    = t / JG;

    float aL[8][4], aR[8][4];
#pragma unroll
    for (int n = 0; n < 8; n++)
#pragma unroll
        for (int j = 0; j < 4; j++) {
            aL[n][j] = 0.f;
            aR[n][j] = bias[jg * 4 + j];
        }

#pragma unroll
    for (int phase = 0; phase < 2; phase++) {
        const int kbase = phase * 32;
        if (phase) __syncthreads();

        {
            const int r  = t % NPB;
            const int c0 = (t / NPB) * KC;
            const int n  = node0 + r;
            const bool ok = (n < NN);
#pragma unroll
            for (int i = 0; i < KC; i += 4) {
                float4 v = ok ? *(const float4*)&h[(size_t)n * 64 + kbase + c0 + i]
                              : make_float4(0.f, 0.f, 0.f, 0.f);
                sh[c0 + i + 0][r] = v.x;
                sh[c0 + i + 1][r] = v.y;
                sh[c0 + i + 2][r] = v.z;
                sh[c0 + i + 3][r] = v.w;
            }
        }
        for (int i = t; i < 32 * DOUT; i += 256) {
            sWl[i] = Wl[kbase * DOUT + i];
            sWr[i] = Wr[kbase * DOUT + i];
        }
        __syncthreads();

#pragma unroll 8
        for (int k = 0; k < 32; k++) {
            const float4 hv0 = *(const float4*)&sh[k][ng * 8];
            const float4 hv1 = *(const float4*)&sh[k][ng * 8 + 4];
            const float4 wl  = *(const float4*)&sWl[k * DOUT + jg * 4];
            const float4 wr  = *(const float4*)&sWr[k * DOUT + jg * 4];
            const float hn[8]  = {hv0.x, hv0.y, hv0.z, hv0.w,
                                  hv1.x, hv1.y, hv1.z, hv1.w};
            const float wlj[4] = {wl.x, wl.y, wl.z, wl.w};
            const float wrj[4] = {wr.x, wr.y, wr.z, wr.w};
#pragma unroll
            for (int n = 0; n < 8; n++) {
#pragma unroll
                for (int j = 0; j < 4; j++) {
                    aL[n][j] = fmaf(hn[n], wlj[j], aL[n][j]);
                    aR[n][j] = fmaf(hn[n], wrj[j], aR[n][j]);
                }
            }
        }
    }

#pragma unroll
    for (int n = 0; n < 8; n++) {
        const int node = node0 + ng * 8 + n;
        if (node < NN) {
            *(float4*)&g_bufA[(size_t)node * DOUT + jg * 4] =
                make_float4(aL[n][0], aL[n][1], aL[n][2], aL[n][3]);
            *(float4*)&g_bufB[(size_t)node * DOUT + jg * 4] =
                make_float4(aR[n][0], aR[n][1], aR[n][2], aR[n][3]);
        }
    }
}

// ---------------------------------------------------------------------------
// Fused gather + epilogue: out[n] = [ELU]( mean_{e in row(n)} yl[col[e]] + yr[n] )
template<int F, bool DO_ELU, bool TO_GH>
__global__ void __launch_bounds__(256)
gather_kernel(float* __restrict__ out_param) {
    constexpr int L = F / 4;               // 16 (F=64) or 8 (F=32)
    const int t    = threadIdx.x;
    const int grp  = t / L;
    const int lane = t % L;
    const int node = blockIdx.x * (256 / L) + grp;
    if (node >= NN) return;

    const int beg = g_rowptr[node];
    const int end = g_rowptr[node + 1];
    const float4* __restrict__ A = (const float4*)g_bufA;

    float4 a0 = make_float4(0.f, 0.f, 0.f, 0.f);
    float4 a1 = make_float4(0.f, 0.f, 0.f, 0.f);
    int e = beg;
    for (; e + 2 <= end; e += 2) {
        int s0 = g_col[e];
        int s1 = g_col[e + 1];
        float4 v0 = A[(size_t)s0 * L + lane];
        float4 v1 = A[(size_t)s1 * L + lane];
        a0.x += v0.x; a0.y += v0.y; a0.z += v0.z; a0.w += v0.w;
        a1.x += v1.x; a1.y += v1.y; a1.z += v1.z; a1.w += v1.w;
    }
    if (e < end) {
        int s0 = g_col[e];
        float4 v0 = A[(size_t)s0 * L + lane];
        a0.x += v0.x; a0.y += v0.y; a0.z += v0.z; a0.w += v0.w;
    }

    const float di = g_deginv[node];
    const float4 r = ((const float4*)g_bufB)[(size_t)node * L + lane];
    float4 o;
    o.x = fmaf(a0.x + a1.x, di, r.x);
    o.y = fmaf(a0.y + a1.y, di, r.y);
    o.z = fmaf(a0.z + a1.z, di, r.z);
    o.w = fmaf(a0.w + a1.w, di, r.w);
    if (DO_ELU) {
        o.x = (o.x > 0.f) ? o.x : expm1f(o.x);
        o.y = (o.y > 0.f) ? o.y : expm1f(o.y);
        o.z = (o.z > 0.f) ? o.z : expm1f(o.z);
        o.w = (o.w > 0.f) ? o.w : expm1f(o.w);
    }
    float* out = TO_GH ? (float*)g_h : out_param;
    ((float4*)out)[(size_t)node * L + lane] = o;
}

// ---------------------------------------------------------------------------
extern "C" void kernel_launch(void* const* d_in, const int* in_sizes, int n_in,
                              void* d_out, int out_size) {
    const float* x   = (const float*)d_in[0];
    const int*   ei  = (const int*)d_in[1];
    const float* Wl0 = (const float*)d_in[2];
    const float* Wr0 = (const float*)d_in[3];
    const float* b0  = (const float*)d_in[4];
    const float* Wl1 = (const float*)d_in[5];
    const float* Wr1 = (const float*)d_in[6];
    const float* b1  = (const float*)d_in[7];
    const float* Wl2 = (const float*)d_in[8];
    const float* Wr2 = (const float*)d_in[9];
    const float* b2  = (const float*)d_in[10];
    float* out = (float*)d_out;

    const int* src = ei;
    const int* dst = ei + NE;

    const int TPB = 256;
    const int gemm_blocks64 = (NN + 127) / 128;   // 782
    const int gemm_blocks32 = (NN + 255) / 256;   // 391
    const int gather_blocks64 = (NN + 15) / 16;
    const int gather_blocks32 = (NN + 31) / 32;

    // Side stream + events for overlapping the CSR build with layer-0 GEMM.
    // Created once (host-side resources only; identical device work per call).
    static cudaStream_t s_side = nullptr;
    static cudaEvent_t  s_fork = nullptr, s_join = nullptr;
    if (s_side == nullptr) {
        cudaStreamCreateWithFlags(&s_side, cudaStreamNonBlocking);
        cudaEventCreateWithFlags(&s_fork, cudaEventDisableTiming);
        cudaEventCreateWithFlags(&s_join, cudaEventDisableTiming);
    }

    // ---- fork: CSR build on side stream, GEMM0 on main stream ----
    cudaEventRecord(s_fork, 0);
    cudaStreamWaitEvent(s_side, s_fork, 0);

    zero_int_kernel<<<(NN + TPB - 1) / TPB, TPB, 0, s_side>>>();
    deg_count_kernel<<<(NE + TPB - 1) / TPB, TPB, 0, s_side>>>(dst);
    scan_a_kernel<<<NBLK, SCAN_BS, 0, s_side>>>();
    scan_b_kernel<<<1, 256, 0, s_side>>>();
    scan_c_kernel<<<(NN + TPB - 1) / TPB, TPB, 0, s_side>>>();
    csr_fill_kernel<<<(NE + TPB - 1) / TPB, TPB, 0, s_side>>>(src, dst);
    cudaEventRecord(s_join, s_side);

    gemm_dual_kernel<64, false><<<gemm_blocks64, 256>>>(x, Wl0, Wr0, b0);

    // ---- join: gather0 needs both CSR and bufA/bufB ----
    cudaStreamWaitEvent(0, s_join, 0);
    gather_kernel<64, true, true><<<gather_blocks64, 256>>>(nullptr);

    // ---- layer 1: 64 -> 64, ELU ----
    gemm_dual_kernel<64, true><<<gemm_blocks64, 256>>>(nullptr, Wl1, Wr1, b1);
    gather_kernel<64, true, true><<<gather_blocks64, 256>>>(nullptr);

    // ---- layer 2: 64 -> 32, no activation, straight to d_out ----
    gemm_dual_kernel<32, true><<<gemm_blocks32, 256>>>(nullptr, Wl2, Wr2, b2);
    gather_kernel<32, false, false><<<gather_blocks32, 256>>>(out);
}